// round 8
// baseline (speedup 1.0000x reference)
#include <cuda_runtime.h>
#include <math.h>

#define H 1024
#define V 50000
#define MAXLEN 35
#define NB 148
#define NT 512
#define NWARP (NT / 32)        // 16 warps per block
#define GWARPS (NB * NWARP)    // 2368 warps total

// -------- device scratch (no allocations allowed) --------
__device__ float g_u[2 * H];
__device__ float g_hg[3 * H];
__device__ float g_comb[H];
__device__ float g_hnew[H];
__device__ float g_logits[V];
__device__ float g_bm[NB];
__device__ float g_bs[NB];
__device__ float g_red[1];
__device__ unsigned g_count[8];
__device__ unsigned g_gen[8];

__device__ __forceinline__ float warp_sum(float v) {
    #pragma unroll
    for (int o = 16; o > 0; o >>= 1) v += __shfl_down_sync(0xffffffffu, v, o);
    return v;
}

// Grid-wide barrier (all NB CTAs resident: 1 CTA/SM).
__device__ __forceinline__ void gsync(int p) {
    __threadfence();
    __syncthreads();
    if (threadIdx.x == 0) {
        volatile unsigned* genp = &g_gen[p];
        unsigned gen = *genp;
        unsigned old = atomicAdd(&g_count[p], 1u);
        if (old == NB - 1) {
            g_count[p] = 0;
            __threadfence();
            atomicAdd(&g_gen[p], 1u);
        } else {
            while (*genp == gen) { __nanosleep(64); }
        }
    }
    __syncthreads();
}

// ---- P3 helpers: row weight prefetch + row reduce/online-logsumexp ----
__device__ __forceinline__ void row_load(int r, const float* __restrict__ Wo,
                                         const float* __restrict__ bo,
                                         int lane, float4 w[8], float& bv) {
    const float4* W = reinterpret_cast<const float4*>(Wo + (long)r * H);
    #pragma unroll
    for (int i = 0; i < 8; i++) w[i] = __ldcs(W + lane + 32 * i);
    if (lane == 0) bv = __ldcs(bo + r);
}

__device__ __forceinline__ void row_step(int r, const float4* __restrict__ h4s,
                                         const float4 w[8], float bv,
                                         float& mx, float& sm, int lane) {
    float a0 = 0.f, a1 = 0.f;
    #pragma unroll
    for (int i = 0; i < 8; i += 2) {
        float4 v0 = h4s[lane + 32 * i];
        float4 v1 = h4s[lane + 32 * (i + 1)];
        a0 += w[i].x * v0.x + w[i].y * v0.y + w[i].z * v0.z + w[i].w * v0.w;
        a1 += w[i+1].x * v1.x + w[i+1].y * v1.y + w[i+1].z * v1.z + w[i+1].w * v1.w;
    }
    float acc = warp_sum(a0 + a1);
    if (lane == 0) {
        float lg = acc + bv;
        g_logits[r] = lg;
        float nm = fmaxf(mx, lg);
        sm = sm * expf(mx - nm) + expf(lg - nm);
        mx = nm;
    }
}

__global__ void __launch_bounds__(NT, 1)
fused_decoder(const int* __restrict__ x, const float* __restrict__ h,
              const float* __restrict__ enc, const float* __restrict__ emb,
              const float* __restrict__ Wa, const float* __restrict__ ba,
              const float* __restrict__ Wc, const float* __restrict__ bc,
              const float* __restrict__ Wih, const float* __restrict__ bih,
              const float* __restrict__ Whh, const float* __restrict__ bhh,
              const float* __restrict__ Wo, const float* __restrict__ bo,
              float* __restrict__ out) {
    __shared__ __align__(16) float sbuf[2 * H];
    __shared__ float s_w[64];
    __shared__ float s_m[NWARP], s_s[NWARP];

    const int tid = threadIdx.x;
    const int wid = tid >> 5;
    const int lane = tid & 31;
    const int b = blockIdx.x;

    // ===== P0: block 0 -> embedding + attention;  blocks 1..147 -> hg = W_hh@h + b_hh
    if (b == 0) {
        const long row = (long)x[0];
        for (int i = tid; i < H; i += NT) {
            float e = emb[row * H + i];
            sbuf[i] = e;
            g_u[i]  = e;
        }
        for (int i = tid; i < H; i += NT) sbuf[H + i] = h[i];
        __syncthreads();

        for (int m = wid; m < MAXLEN; m += NWARP) {
            const float* Wr = Wa + (long)m * (2 * H);
            float acc = 0.f;
            for (int k = lane; k < 2 * H; k += 32) acc += __ldcs(Wr + k) * sbuf[k];
            acc = warp_sum(acc);
            if (lane == 0) s_w[m] = acc + ba[m];
        }
        __syncthreads();

        if (tid == 0) {
            float mx = -1e30f;
            for (int m = 0; m < MAXLEN; m++) mx = fmaxf(mx, s_w[m]);
            float s = 0.f;
            for (int m = 0; m < MAXLEN; m++) { float e = expf(s_w[m] - mx); s_w[m] = e; s += e; }
            float inv = 1.f / s;
            for (int m = 0; m < MAXLEN; m++) s_w[m] *= inv;
        }
        __syncthreads();

        if (tid < MAXLEN) out[V + H + tid] = s_w[tid];

        for (int i = tid; i < H; i += NT) {
            float acc = 0.f;
            #pragma unroll
            for (int m = 0; m < MAXLEN; m++) acc += s_w[m] * enc[m * H + i];
            g_u[H + i] = acc;
        }
    } else {
        const int gw = (b - 1) * NWARP + wid;
        const float4* hv = reinterpret_cast<const float4*>(h);
        for (int r = gw; r < 3 * H; r += (NB - 1) * NWARP) {
            const float4* Wr = reinterpret_cast<const float4*>(Whh + (long)r * H);
            float acc = 0.f;
            #pragma unroll 8
            for (int c = lane; c < H / 4; c += 32) {
                float4 w = __ldcs(Wr + c); float4 v = hv[c];
                acc += w.x * v.x + w.y * v.y + w.z * v.z + w.w * v.w;
            }
            acc = warp_sum(acc);
            if (lane == 0) g_hg[r] = acc + bhh[r];
        }
    }
    gsync(0);

    // ===== P1: comb = relu(W_comb @ u + b_comb)
    for (int i = tid; i < 2 * H; i += NT) sbuf[i] = g_u[i];
    __syncthreads();
    {
        const int r = b + NB * wid;
        if (r < H) {
            const float4* Wr = reinterpret_cast<const float4*>(Wc + (long)r * (2 * H));
            const float4* uv = reinterpret_cast<const float4*>(sbuf);
            float acc = 0.f;
            #pragma unroll 8
            for (int c = lane; c < (2 * H) / 4; c += 32) {
                float4 w = __ldcs(Wr + c); float4 v = uv[c];
                acc += w.x * v.x + w.y * v.y + w.z * v.z + w.w * v.w;
            }
            acc = warp_sum(acc);
            if (lane == 0) g_comb[r] = fmaxf(acc + bc[r], 0.f);
        }
    }
    gsync(1);

    // ===== P2: GRU gates + elementwise update fused; warp owns one j
    __syncthreads();
    for (int i = tid; i < H; i += NT) sbuf[i] = g_comb[i];
    __syncthreads();
    {
        const int j = b + NB * wid;
        if (j < H) {
            const float4* W0 = reinterpret_cast<const float4*>(Wih + (long)j * H);
            const float4* W1 = reinterpret_cast<const float4*>(Wih + (long)(H + j) * H);
            const float4* W2 = reinterpret_cast<const float4*>(Wih + (long)(2 * H + j) * H);
            const float4* cv = reinterpret_cast<const float4*>(sbuf);
            float a0 = 0.f, a1 = 0.f, a2 = 0.f;
            #pragma unroll 4
            for (int c = lane; c < H / 4; c += 32) {
                float4 v = cv[c];
                float4 w0 = __ldcs(W0 + c), w1 = __ldcs(W1 + c), w2 = __ldcs(W2 + c);
                a0 += w0.x * v.x + w0.y * v.y + w0.z * v.z + w0.w * v.w;
                a1 += w1.x * v.x + w1.y * v.y + w1.z * v.z + w1.w * v.w;
                a2 += w2.x * v.x + w2.y * v.y + w2.z * v.z + w2.w * v.w;
            }
            a0 = warp_sum(a0); a1 = warp_sum(a1); a2 = warp_sum(a2);
            if (lane == 0) {
                float xr = a0 + bih[j];
                float xz = a1 + bih[H + j];
                float xn = a2 + bih[2 * H + j];
                float rr = 1.f / (1.f + expf(-(xr + g_hg[j])));
                float zz = 1.f / (1.f + expf(-(xz + g_hg[H + j])));
                float nn = tanhf(xn + rr * g_hg[2 * H + j]);
                float hv = (1.f - zz) * nn + zz * h[j];
                g_hnew[j] = hv;
                out[V + j] = hv;
            }
        }
    }
    gsync(2);

    // ===== P3: logits GEMV, software-pipelined (double-buffered row weights)
    __syncthreads();
    for (int i = tid; i < H; i += NT) sbuf[i] = g_hnew[i];
    __syncthreads();
    {
        const float4* h4s = reinterpret_cast<const float4*>(sbuf);
        const int gw = b * NWARP + wid;                  // 0..2367 < V
        float mx = -1e30f, sm = 0.f;

        float4 wA[8], wB[8];
        float bA = 0.f, bB = 0.f;

        int r = gw;
        row_load(r, Wo, bo, lane, wA, bA);               // prime the pipe
        while (r < V) {
            const int r1 = r + GWARPS;
            if (r1 < V) row_load(r1, Wo, bo, lane, wB, bB);
            row_step(r, h4s, wA, bA, mx, sm, lane);      // overlaps wB loads
            if (r1 < V) {
                const int r2 = r1 + GWARPS;
                if (r2 < V) row_load(r2, Wo, bo, lane, wA, bA);
                row_step(r1, h4s, wB, bB, mx, sm, lane); // overlaps wA loads
                r = r2;
            } else {
                r = r1;
            }
        }

        if (lane == 0) { s_m[wid] = mx; s_s[wid] = sm; }
        __syncthreads();
        if (tid == 0) {
            float M = -1e30f, S = 0.f;
            #pragma unroll
            for (int w = 0; w < NWARP; w++) {
                float m2 = s_m[w], s2 = s_s[w];
                float nm = fmaxf(M, m2);
                S = S * expf(M - nm) + s2 * expf(m2 - nm);
                M = nm;
            }
            g_bm[b] = M; g_bs[b] = S;
        }
    }
    gsync(3);

    // ===== P4: block 0 warp 0 reduces 148 (m,s) pairs
    if (b == 0 && wid == 0) {
        float M = -1e30f, S = 0.f;
        for (int i = lane; i < NB; i += 32) {
            float m2 = g_bm[i], s2 = g_bs[i];
            float nm = fmaxf(M, m2);
            S = S * expf(M - nm) + s2 * expf(m2 - nm);
            M = nm;
        }
        #pragma unroll
        for (int o = 16; o > 0; o >>= 1) {
            float m2 = __shfl_down_sync(0xffffffffu, M, o);
            float s2 = __shfl_down_sync(0xffffffffu, S, o);
            float nm = fmaxf(M, m2);
            S = S * expf(M - nm) + s2 * expf(m2 - nm);
            M = nm;
        }
        if (lane == 0) g_red[0] = M + logf(S);
    }
    gsync(4);

    // ===== P5: logp = logits - (M + log S)
    {
        const float off = g_red[0];
        for (int v = b * NT + tid; v < V; v += NB * NT) out[v] = g_logits[v] - off;
    }
}

extern "C" void kernel_launch(void* const* d_in, const int* in_sizes, int n_in,
                              void* d_out, int out_size) {
    const int*   x   = (const int*)  d_in[0];
    const float* h   = (const float*)d_in[1];
    const float* enc = (const float*)d_in[3];
    const float* emb = (const float*)d_in[4];
    const float* Wa  = (const float*)d_in[5];
    const float* ba  = (const float*)d_in[6];
    const float* Wc  = (const float*)d_in[7];
    const float* bc  = (const float*)d_in[8];
    const float* Wih = (const float*)d_in[9];
    const float* bih = (const float*)d_in[10];
    const float* Whh = (const float*)d_in[11];
    const float* bhh = (const float*)d_in[12];
    const float* Wo  = (const float*)d_in[13];
    const float* bo  = (const float*)d_in[14];
    float* out = (float*)d_out;

    fused_decoder<<<NB, NT>>>(x, h, enc, emb, Wa, ba, Wc, bc,
                              Wih, bih, Whh, bhh, Wo, bo, out);
}

// round 13
// speedup vs baseline: 1.1143x; 1.1143x over previous
#include <cuda_runtime.h>
#include <cstdint>
#include <math.h>

#define H 1024
#define V 50000
#define MAXLEN 35
#define NB 148
#define NT 512
#define NWARP (NT / 32)        // 16 warps per block
#define GWARPS (NB * NWARP)    // 2368 warps total
#define NSTAGE 3
#define ROWB 4096              // bytes per row of W_out
#define SMEM_DYN (NWARP * NSTAGE * ROWB)   // 192 KB staging ring (union with sbuf)

// -------- device scratch (no allocations allowed) --------
__device__ float g_u[2 * H];
__device__ float g_hg[3 * H];
__device__ float g_comb[H];
__device__ float g_hnew[H];
__device__ float g_logits[V];
__device__ float g_bm[NB];
__device__ float g_bs[NB];
__device__ float g_red[1];
__device__ unsigned g_count[8];
__device__ unsigned g_gen[8];

__device__ __forceinline__ float warp_sum(float v) {
    #pragma unroll
    for (int o = 16; o > 0; o >>= 1) v += __shfl_down_sync(0xffffffffu, v, o);
    return v;
}

// Grid-wide barrier (all NB CTAs resident: 1 CTA/SM).
__device__ __forceinline__ void gsync(int p) {
    __threadfence();
    __syncthreads();
    if (threadIdx.x == 0) {
        volatile unsigned* genp = &g_gen[p];
        unsigned gen = *genp;
        unsigned old = atomicAdd(&g_count[p], 1u);
        if (old == NB - 1) {
            g_count[p] = 0;
            __threadfence();
            atomicAdd(&g_gen[p], 1u);
        } else {
            while (*genp == gen) { __nanosleep(64); }
        }
    }
    __syncthreads();
}

// ---- cp.async primitives ----
__device__ __forceinline__ void cpa16(unsigned int s, const void* g) {
    asm volatile("cp.async.cg.shared.global [%0], [%1], 16;" :: "r"(s), "l"(g) : "memory");
}
__device__ __forceinline__ void cpa4(unsigned int s, const void* g) {
    asm volatile("cp.async.ca.shared.global [%0], [%1], 4;" :: "r"(s), "l"(g) : "memory");
}
#define CP_COMMIT() asm volatile("cp.async.commit_group;" ::: "memory")
template <int N>
__device__ __forceinline__ void cp_wait() {
    asm volatile("cp.async.wait_group %0;" :: "n"(N) : "memory");
}

__global__ void __launch_bounds__(NT, 1)
fused_decoder(const int* __restrict__ x, const float* __restrict__ h,
              const float* __restrict__ enc, const float* __restrict__ emb,
              const float* __restrict__ Wa, const float* __restrict__ ba,
              const float* __restrict__ Wc, const float* __restrict__ bc,
              const float* __restrict__ Wih, const float* __restrict__ bih,
              const float* __restrict__ Whh, const float* __restrict__ bhh,
              const float* __restrict__ Wo, const float* __restrict__ bo,
              float* __restrict__ out) {
    extern __shared__ __align__(16) char dynsm[];   // P0-P2: sbuf (8KB); P3: staging ring
    float* sbuf = reinterpret_cast<float*>(dynsm);
    __shared__ float s_w[64];
    __shared__ float s_m[NWARP], s_s[NWARP];
    __shared__ float bo_s[NWARP * NSTAGE];

    const int tid = threadIdx.x;
    const int wid = tid >> 5;
    const int lane = tid & 31;
    const int b = blockIdx.x;

    // ===== P0: block 0 -> embedding + attention;  blocks 1..147 -> hg = W_hh@h + b_hh
    if (b == 0) {
        const long row = (long)x[0];
        for (int i = tid; i < H; i += NT) {
            float e = emb[row * H + i];
            sbuf[i] = e;
            g_u[i]  = e;
        }
        for (int i = tid; i < H; i += NT) sbuf[H + i] = h[i];
        __syncthreads();

        for (int m = wid; m < MAXLEN; m += NWARP) {
            const float* Wr = Wa + (long)m * (2 * H);
            float acc = 0.f;
            for (int k = lane; k < 2 * H; k += 32) acc += __ldcs(Wr + k) * sbuf[k];
            acc = warp_sum(acc);
            if (lane == 0) s_w[m] = acc + ba[m];
        }
        __syncthreads();

        if (tid == 0) {
            float mx = -1e30f;
            for (int m = 0; m < MAXLEN; m++) mx = fmaxf(mx, s_w[m]);
            float s = 0.f;
            for (int m = 0; m < MAXLEN; m++) { float e = expf(s_w[m] - mx); s_w[m] = e; s += e; }
            float inv = 1.f / s;
            for (int m = 0; m < MAXLEN; m++) s_w[m] *= inv;
        }
        __syncthreads();

        if (tid < MAXLEN) out[V + H + tid] = s_w[tid];

        for (int i = tid; i < H; i += NT) {
            float acc = 0.f;
            #pragma unroll
            for (int m = 0; m < MAXLEN; m++) acc += s_w[m] * enc[m * H + i];
            g_u[H + i] = acc;
        }
    } else {
        const int gw = (b - 1) * NWARP + wid;
        const float4* hv = reinterpret_cast<const float4*>(h);
        for (int r = gw; r < 3 * H; r += (NB - 1) * NWARP) {
            const float4* Wr = reinterpret_cast<const float4*>(Whh + (long)r * H);
            float acc = 0.f;
            #pragma unroll 8
            for (int c = lane; c < H / 4; c += 32) {
                float4 w = __ldcs(Wr + c); float4 v = hv[c];
                acc += w.x * v.x + w.y * v.y + w.z * v.z + w.w * v.w;
            }
            acc = warp_sum(acc);
            if (lane == 0) g_hg[r] = acc + bhh[r];
        }
    }
    gsync(0);

    // ===== P1: comb = relu(W_comb @ u + b_comb)
    for (int i = tid; i < 2 * H; i += NT) sbuf[i] = g_u[i];
    __syncthreads();
    {
        const int r = b + NB * wid;
        if (r < H) {
            const float4* Wr = reinterpret_cast<const float4*>(Wc + (long)r * (2 * H));
            const float4* uv = reinterpret_cast<const float4*>(sbuf);
            float acc = 0.f;
            #pragma unroll 8
            for (int c = lane; c < (2 * H) / 4; c += 32) {
                float4 w = __ldcs(Wr + c); float4 v = uv[c];
                acc += w.x * v.x + w.y * v.y + w.z * v.z + w.w * v.w;
            }
            acc = warp_sum(acc);
            if (lane == 0) g_comb[r] = fmaxf(acc + bc[r], 0.f);
        }
    }
    gsync(1);

    // ===== P2: GRU gates + elementwise update fused; warp owns one j
    __syncthreads();
    for (int i = tid; i < H; i += NT) sbuf[i] = g_comb[i];
    __syncthreads();
    {
        const int j = b + NB * wid;
        if (j < H) {
            const float4* W0 = reinterpret_cast<const float4*>(Wih + (long)j * H);
            const float4* W1 = reinterpret_cast<const float4*>(Wih + (long)(H + j) * H);
            const float4* W2 = reinterpret_cast<const float4*>(Wih + (long)(2 * H + j) * H);
            const float4* cv = reinterpret_cast<const float4*>(sbuf);
            float a0 = 0.f, a1 = 0.f, a2 = 0.f;
            #pragma unroll 4
            for (int c = lane; c < H / 4; c += 32) {
                float4 v = cv[c];
                float4 w0 = __ldcs(W0 + c), w1 = __ldcs(W1 + c), w2 = __ldcs(W2 + c);
                a0 += w0.x * v.x + w0.y * v.y + w0.z * v.z + w0.w * v.w;
                a1 += w1.x * v.x + w1.y * v.y + w1.z * v.z + w1.w * v.w;
                a2 += w2.x * v.x + w2.y * v.y + w2.z * v.z + w2.w * v.w;
            }
            a0 = warp_sum(a0); a1 = warp_sum(a1); a2 = warp_sum(a2);
            if (lane == 0) {
                float xr = a0 + bih[j];
                float xz = a1 + bih[H + j];
                float xn = a2 + bih[2 * H + j];
                float rr = 1.f / (1.f + expf(-(xr + g_hg[j])));
                float zz = 1.f / (1.f + expf(-(xz + g_hg[H + j])));
                float nn = tanhf(xn + rr * g_hg[2 * H + j]);
                float hv = (1.f - zz) * nn + zz * h[j];
                g_hnew[j] = hv;
                out[V + j] = hv;
            }
        }
    }
    gsync(2);   // includes __syncthreads: sbuf reads done before staging reuses dynsm

    // ===== P3: logits GEMV via cp.async 3-stage smem pipeline + online logsumexp
    {
        // h_new in registers: 8 float4 per lane (lane-strided), reused every row
        const float4* h4 = reinterpret_cast<const float4*>(g_hnew);
        float4 hr[8];
        #pragma unroll
        for (int i = 0; i < 8; i++) hr[i] = h4[lane + 32 * i];

        char* ring = dynsm + wid * (NSTAGE * ROWB);         // 12KB private per warp
        unsigned int ring_u = (unsigned int)__cvta_generic_to_shared(ring);
        unsigned int bo_u   = (unsigned int)__cvta_generic_to_shared(&bo_s[wid * NSTAGE]);

        const int gw = b * NWARP + wid;                     // 0..2367 < V
        const int nrows = (V - gw + GWARPS - 1) / GWARPS;   // 21 or 22

        // prologue: stage rows 0..NSTAGE-1
        #pragma unroll
        for (int k = 0; k < NSTAGE; k++) {
            if (k < nrows) {
                const int r = gw + k * GWARPS;
                const char* g = (const char*)(Wo + (long)r * H) + lane * 16;
                unsigned int s = ring_u + k * ROWB + lane * 16;
                #pragma unroll
                for (int j = 0; j < 8; j++) cpa16(s + j * 512, g + j * 512);
                if (lane == 0) cpa4(bo_u + k * 4, bo + r);
            }
            CP_COMMIT();
        }

        float mx = -1e30f, sm = 0.f;
        int slot = 0;
        for (int k = 0; k < nrows; k++) {
            cp_wait<NSTAGE - 1>();                          // slot's row is resident

            const float4* buf = reinterpret_cast<const float4*>(ring + slot * ROWB);
            float a0 = 0.f, a1 = 0.f;
            #pragma unroll
            for (int i = 0; i < 8; i += 2) {
                float4 w0 = buf[lane + 32 * i];
                float4 w1 = buf[lane + 32 * (i + 1)];
                a0 += w0.x * hr[i].x + w0.y * hr[i].y + w0.z * hr[i].z + w0.w * hr[i].w;
                a1 += w1.x * hr[i+1].x + w1.y * hr[i+1].y + w1.z * hr[i+1].z + w1.w * hr[i+1].w;
            }
            float acc = warp_sum(a0 + a1);
            if (lane == 0) {
                const int r = gw + k * GWARPS;
                float lg = acc + bo_s[wid * NSTAGE + slot];
                g_logits[r] = lg;
                float nm = fmaxf(mx, lg);
                sm = sm * expf(mx - nm) + expf(lg - nm);
                mx = nm;
            }

            // refill the slot just consumed with row k+NSTAGE
            const int kn = k + NSTAGE;
            if (kn < nrows) {
                const int rn = gw + kn * GWARPS;
                const char* g = (const char*)(Wo + (long)rn * H) + lane * 16;
                unsigned int s = ring_u + slot * ROWB + lane * 16;
                #pragma unroll
                for (int j = 0; j < 8; j++) cpa16(s + j * 512, g + j * 512);
                if (lane == 0) cpa4(bo_u + slot * 4, bo + rn);
            }
            CP_COMMIT();                                    // keep group count uniform

            slot = (slot + 1 == NSTAGE) ? 0 : slot + 1;
        }
        cp_wait<0>();                                       // drain before ring reuse

        if (lane == 0) { s_m[wid] = mx; s_s[wid] = sm; }
        __syncthreads();
        if (tid == 0) {
            float M = -1e30f, S = 0.f;
            #pragma unroll
            for (int w = 0; w < NWARP; w++) {
                float m2 = s_m[w], s2 = s_s[w];
                float nm = fmaxf(M, m2);
                S = S * expf(M - nm) + s2 * expf(m2 - nm);
                M = nm;
            }
            g_bm[b] = M; g_bs[b] = S;
        }
    }
    gsync(3);

    // ===== P4: block 0 warp 0 reduces 148 (m,s) pairs
    if (b == 0 && wid == 0) {
        float M = -1e30f, S = 0.f;
        for (int i = lane; i < NB; i += 32) {
            float m2 = g_bm[i], s2 = g_bs[i];
            float nm = fmaxf(M, m2);
            S = S * expf(M - nm) + s2 * expf(m2 - nm);
            M = nm;
        }
        #pragma unroll
        for (int o = 16; o > 0; o >>= 1) {
            float m2 = __shfl_down_sync(0xffffffffu, M, o);
            float s2 = __shfl_down_sync(0xffffffffu, S, o);
            float nm = fmaxf(M, m2);
            S = S * expf(M - nm) + s2 * expf(m2 - nm);
            M = nm;
        }
        if (lane == 0) g_red[0] = M + logf(S);
    }
    gsync(4);

    // ===== P5: logp = logits - (M + log S)
    {
        const float off = g_red[0];
        for (int v = b * NT + tid; v < V; v += NB * NT) out[v] = g_logits[v] - off;
    }
}

extern "C" void kernel_launch(void* const* d_in, const int* in_sizes, int n_in,
                              void* d_out, int out_size) {
    const int*   x   = (const int*)  d_in[0];
    const float* h   = (const float*)d_in[1];
    const float* enc = (const float*)d_in[3];
    const float* emb = (const float*)d_in[4];
    const float* Wa  = (const float*)d_in[5];
    const float* ba  = (const float*)d_in[6];
    const float* Wc  = (const float*)d_in[7];
    const float* bc  = (const float*)d_in[8];
    const float* Wih = (const float*)d_in[9];
    const float* bih = (const float*)d_in[10];
    const float* Whh = (const float*)d_in[11];
    const float* bhh = (const float*)d_in[12];
    const float* Wo  = (const float*)d_in[13];
    const float* bo  = (const float*)d_in[14];
    float* out = (float*)d_out;

    cudaFuncSetAttribute(fused_decoder,
                         cudaFuncAttributeMaxDynamicSharedMemorySize, SMEM_DYN);
    fused_decoder<<<NB, NT, SMEM_DYN>>>(x, h, enc, emb, Wa, ba, Wc, bc,
                                        Wih, bih, Whh, bhh, Wo, bo, out);
}

// round 16
// speedup vs baseline: 1.1860x; 1.0643x over previous
#include <cuda_runtime.h>
#include <cstdint>
#include <math.h>

#define H 1024
#define V 50000
#define MAXLEN 35
#define NBLK5 (V / 8)          // 6250 blocks, 8 rows each, exact

// -------- device scratch (no allocations allowed) --------
__device__ __align__(16) float g_u[2 * H];       // [embedded ; attn_applied]
__device__ float g_hg[3 * H];                    // W_hh @ h + b_hh
__device__ __align__(16) float g_comb[H];        // relu(combine)
__device__ __align__(16) float g_hnew[H];        // new hidden
__device__ __align__(16) float g_logits[V];      // logits
__device__ float g_bm[NBLK5];                    // per-block max
__device__ float g_bs[NBLK5];                    // per-block sum exp(l-max)
__device__ float g_red[1];                       // M + log(S)

__device__ __forceinline__ float warp_sum(float v) {
    #pragma unroll
    for (int o = 16; o > 0; o >>= 1) v += __shfl_down_sync(0xffffffffu, v, o);
    return v;
}

// K1: block 0 -> embedding + attention + attn_applied; blocks 1..147 -> hg = W_hh@h+b_hh
__global__ void __launch_bounds__(512, 1)
k1_attn_hg(const int* __restrict__ x, const float* __restrict__ h,
           const float* __restrict__ enc, const float* __restrict__ emb,
           const float* __restrict__ Wa, const float* __restrict__ ba,
           const float* __restrict__ Whh, const float* __restrict__ bhh,
           float* __restrict__ out) {
    const int tid = threadIdx.x, wid = tid >> 5, lane = tid & 31;
    if (blockIdx.x == 0) {
        __shared__ float s_in[2 * H];
        __shared__ float s_w[64];
        const long row = (long)x[0];
        for (int i = tid; i < H; i += 512) {
            float e = emb[row * H + i];
            s_in[i] = e;
            g_u[i]  = e;
        }
        for (int i = tid; i < H; i += 512) s_in[H + i] = h[i];
        __syncthreads();

        for (int m = wid; m < MAXLEN; m += 16) {
            const float* Wr = Wa + (long)m * (2 * H);
            float acc = 0.f;
            for (int k = lane; k < 2 * H; k += 32) acc += __ldcs(Wr + k) * s_in[k];
            acc = warp_sum(acc);
            if (lane == 0) s_w[m] = acc + ba[m];
        }
        __syncthreads();

        if (tid == 0) {
            float mx = -1e30f;
            for (int m = 0; m < MAXLEN; m++) mx = fmaxf(mx, s_w[m]);
            float s = 0.f;
            for (int m = 0; m < MAXLEN; m++) { float e = expf(s_w[m] - mx); s_w[m] = e; s += e; }
            float inv = 1.f / s;
            for (int m = 0; m < MAXLEN; m++) s_w[m] *= inv;
        }
        __syncthreads();

        if (tid < MAXLEN) out[V + H + tid] = s_w[tid];

        for (int i = tid; i < H; i += 512) {
            float acc = 0.f;
            #pragma unroll
            for (int m = 0; m < MAXLEN; m++) acc += s_w[m] * enc[m * H + i];
            g_u[H + i] = acc;
        }
    } else {
        const int gw = (blockIdx.x - 1) * 16 + wid;        // 0..2351
        const float4* hv = reinterpret_cast<const float4*>(h);
        for (int r = gw; r < 3 * H; r += 147 * 16) {
            const float4* Wr = reinterpret_cast<const float4*>(Whh + (long)r * H);
            float acc = 0.f;
            #pragma unroll 8
            for (int c = lane; c < H / 4; c += 32) {
                float4 w = __ldcs(Wr + c); float4 v = hv[c];
                acc += w.x * v.x + w.y * v.y + w.z * v.z + w.w * v.w;
            }
            acc = warp_sum(acc);
            if (lane == 0) g_hg[r] = acc + bhh[r];
        }
    }
}

// K2: comb = relu(W_comb @ u + b_comb); 128 blocks x 256 thr; warp per row
__global__ void __launch_bounds__(256)
k2_comb(const float* __restrict__ Wc, const float* __restrict__ bc) {
    __shared__ float4 s_u[(2 * H) / 4];
    const int tid = threadIdx.x, wid = tid >> 5, lane = tid & 31;
    const float4* u4 = reinterpret_cast<const float4*>(g_u);
    s_u[tid] = u4[tid];
    s_u[tid + 256] = u4[tid + 256];
    __syncthreads();

    const int r = blockIdx.x * 8 + wid;                    // 0..1023
    const float4* Wr = reinterpret_cast<const float4*>(Wc + (long)r * (2 * H));
    float acc = 0.f;
    #pragma unroll 8
    for (int c = lane; c < (2 * H) / 4; c += 32) {
        float4 w = __ldcs(Wr + c), v = s_u[c];
        acc += w.x * v.x + w.y * v.y + w.z * v.z + w.w * v.w;
    }
    acc = warp_sum(acc);
    if (lane == 0) g_comb[r] = fmaxf(acc + bc[r], 0.f);
}

// K3: GRU gates (3 W_ih rows per warp) + elementwise update; 128 blocks x 256 thr
__global__ void __launch_bounds__(256)
k3_gru(const float* __restrict__ Wih, const float* __restrict__ bih,
       const float* __restrict__ h, float* __restrict__ out) {
    __shared__ float4 s_c[H / 4];
    const int tid = threadIdx.x, wid = tid >> 5, lane = tid & 31;
    s_c[tid] = reinterpret_cast<const float4*>(g_comb)[tid];
    __syncthreads();

    const int j = blockIdx.x * 8 + wid;                    // 0..1023
    const float4* W0 = reinterpret_cast<const float4*>(Wih + (long)j * H);
    const float4* W1 = reinterpret_cast<const float4*>(Wih + (long)(H + j) * H);
    const float4* W2 = reinterpret_cast<const float4*>(Wih + (long)(2 * H + j) * H);
    float a0 = 0.f, a1 = 0.f, a2 = 0.f;
    #pragma unroll 4
    for (int c = lane; c < H / 4; c += 32) {
        float4 v = s_c[c];
        float4 w0 = __ldcs(W0 + c), w1 = __ldcs(W1 + c), w2 = __ldcs(W2 + c);
        a0 += w0.x * v.x + w0.y * v.y + w0.z * v.z + w0.w * v.w;
        a1 += w1.x * v.x + w1.y * v.y + w1.z * v.z + w1.w * v.w;
        a2 += w2.x * v.x + w2.y * v.y + w2.z * v.z + w2.w * v.w;
    }
    a0 = warp_sum(a0); a1 = warp_sum(a1); a2 = warp_sum(a2);
    if (lane == 0) {
        float xr = a0 + bih[j];
        float xz = a1 + bih[H + j];
        float xn = a2 + bih[2 * H + j];
        float rr = 1.f / (1.f + expf(-(xr + g_hg[j])));
        float zz = 1.f / (1.f + expf(-(xz + g_hg[H + j])));
        float nn = tanhf(xn + rr * g_hg[2 * H + j]);
        float hv = (1.f - zz) * nn + zz * h[j];
        g_hnew[j] = hv;
        out[V + j] = hv;
    }
}

// K5: logits = W_out @ hnew + b_out; 6250 blocks x 256 thr; warp per row;
//     per-block (max, sum exp) partials
__global__ void __launch_bounds__(256)
k5_logits(const float* __restrict__ Wo, const float* __restrict__ bo) {
    __shared__ float4 s_h[H / 4];
    __shared__ float s_l[8];
    const int tid = threadIdx.x, wid = tid >> 5, lane = tid & 31;
    s_h[tid] = reinterpret_cast<const float4*>(g_hnew)[tid];
    __syncthreads();

    const int r = blockIdx.x * 8 + wid;                    // < V exactly
    float bv = 0.f;
    if (lane == 0) bv = __ldcs(bo + r);                    // overlaps the row loads
    const float4* Wr = reinterpret_cast<const float4*>(Wo + (long)r * H);
    float acc = 0.f;
    #pragma unroll
    for (int c = lane; c < H / 4; c += 32) {
        float4 w = __ldcs(Wr + c), v = s_h[c];
        acc += w.x * v.x + w.y * v.y + w.z * v.z + w.w * v.w;
    }
    acc = warp_sum(acc);
    if (lane == 0) {
        float lg = acc + bv;
        g_logits[r] = lg;
        s_l[wid] = lg;
    }
    __syncthreads();
    if (tid == 0) {
        float m = s_l[0];
        #pragma unroll
        for (int w = 1; w < 8; w++) m = fmaxf(m, s_l[w]);
        float s = 0.f;
        #pragma unroll
        for (int w = 0; w < 8; w++) s += expf(s_l[w] - m);
        g_bm[blockIdx.x] = m;
        g_bs[blockIdx.x] = s;
    }
}

// K6: reduce 6250 (m,s) pairs -> M + log(S); 1 block x 1024 thr
__global__ void __launch_bounds__(1024)
k6_red() {
    __shared__ float sm[32], ss[32];
    const int tid = threadIdx.x, lane = tid & 31, w = tid >> 5;
    float M = -1e30f, S = 0.f;
    for (int i = tid; i < NBLK5; i += 1024) {
        float m2 = g_bm[i], s2 = g_bs[i];
        float nm = fmaxf(M, m2);
        S = S * expf(M - nm) + s2 * expf(m2 - nm);
        M = nm;
    }
    #pragma unroll
    for (int o = 16; o > 0; o >>= 1) {
        float m2 = __shfl_down_sync(0xffffffffu, M, o);
        float s2 = __shfl_down_sync(0xffffffffu, S, o);
        float nm = fmaxf(M, m2);
        S = S * expf(M - nm) + s2 * expf(m2 - nm);
        M = nm;
    }
    if (lane == 0) { sm[w] = M; ss[w] = S; }
    __syncthreads();
    if (tid < 32) {
        float m1 = sm[tid], s1 = ss[tid];
        #pragma unroll
        for (int o = 16; o > 0; o >>= 1) {
            float m2 = __shfl_down_sync(0xffffffffu, m1, o);
            float s2 = __shfl_down_sync(0xffffffffu, s1, o);
            float nm = fmaxf(m1, m2);
            s1 = s1 * expf(m1 - nm) + s2 * expf(m2 - nm);
            m1 = nm;
        }
        if (tid == 0) g_red[0] = m1 + logf(s1);
    }
}

// K7: logp = logits - (M + log S); vectorized
__global__ void __launch_bounds__(256)
k7_out(float* __restrict__ out) {
    const int i = blockIdx.x * 256 + threadIdx.x;          // float4 index
    const float off = g_red[0];
    if (i < V / 4) {
        float4 l = reinterpret_cast<const float4*>(g_logits)[i];
        float4 o;
        o.x = l.x - off; o.y = l.y - off; o.z = l.z - off; o.w = l.w - off;
        reinterpret_cast<float4*>(out)[i] = o;
    }
}

extern "C" void kernel_launch(void* const* d_in, const int* in_sizes, int n_in,
                              void* d_out, int out_size) {
    const int*   x   = (const int*)  d_in[0];
    const float* h   = (const float*)d_in[1];   // h_state (1,1,H)
    const float* enc = (const float*)d_in[3];   // encoder_outputs
    const float* emb = (const float*)d_in[4];
    const float* Wa  = (const float*)d_in[5];
    const float* ba  = (const float*)d_in[6];
    const float* Wc  = (const float*)d_in[7];
    const float* bc  = (const float*)d_in[8];
    const float* Wih = (const float*)d_in[9];
    const float* bih = (const float*)d_in[10];
    const float* Whh = (const float*)d_in[11];
    const float* bhh = (const float*)d_in[12];
    const float* Wo  = (const float*)d_in[13];
    const float* bo  = (const float*)d_in[14];
    float* out = (float*)d_out;

    k1_attn_hg<<<148, 512>>>(x, h, enc, emb, Wa, ba, Whh, bhh, out);
    k2_comb<<<128, 256>>>(Wc, bc);
    k3_gru<<<128, 256>>>(Wih, bih, h, out);
    k5_logits<<<NBLK5, 256>>>(Wo, bo);
    k6_red<<<1, 1024>>>();
    k7_out<<<(V / 4 + 255) / 256, 256>>>(out);
}

// round 17
// speedup vs baseline: 1.4870x; 1.2539x over previous
#include <cuda_runtime.h>
#include <cstdint>
#include <math.h>

#define H 1024
#define V 50000
#define MAXLEN 35
#define NBLK5 (V / 8)          // 6250 blocks, 8 rows each, exact

// -------- device scratch (no allocations allowed) --------
__device__ __align__(16) float g_u[2 * H];       // [embedded ; attn_applied]
__device__ float g_scores[64];                   // raw attention scores
__device__ float g_hg[3 * H];                    // W_hh @ h + b_hh
__device__ __align__(16) float g_comb[H];        // relu(combine)
__device__ __align__(16) float g_hnew[H];        // new hidden
__device__ __align__(16) float g_logits[V];      // logits
__device__ float g_bm[NBLK5];                    // per-block max
__device__ float g_bs[NBLK5];                    // per-block sum exp(l-max)
__device__ float g_red[1];                       // M + log(S)

__device__ __forceinline__ float warp_sum(float v) {
    #pragma unroll
    for (int o = 16; o > 0; o >>= 1) v += __shfl_down_sync(0xffffffffu, v, o);
    return v;
}

// K1: blocks 0..34 -> attention score rows; blocks 35..3106 -> hg = W_hh@h + b_hh rows
__global__ void __launch_bounds__(256)
k1_scores_hg(const int* __restrict__ x, const float* __restrict__ h,
             const float* __restrict__ emb,
             const float* __restrict__ Wa, const float* __restrict__ ba,
             const float* __restrict__ Whh, const float* __restrict__ bhh) {
    __shared__ float s_r[8];
    const int tid = threadIdx.x, wid = tid >> 5, lane = tid & 31;
    const int b = blockIdx.x;

    if (b < MAXLEN) {
        // score m = Wa[m,:2048] . [emb[x]; h] + ba[m]
        const long row = (long)x[0];
        const float* Wr = Wa + (long)b * (2 * H);
        float acc = 0.f;
        #pragma unroll
        for (int k = tid; k < 2 * H; k += 256) {
            float u = (k < H) ? emb[row * H + k] : h[k - H];
            acc += __ldcs(Wr + k) * u;
        }
        acc = warp_sum(acc);
        if (lane == 0) s_r[wid] = acc;
        __syncthreads();
        if (tid == 0) {
            float s = 0.f;
            #pragma unroll
            for (int w = 0; w < 8; w++) s += s_r[w];
            g_scores[b] = s + ba[b];
        }
    } else {
        const int r = b - MAXLEN;                          // 0..3071
        const float4* Wr = reinterpret_cast<const float4*>(Whh + (long)r * H);
        const float4* hv = reinterpret_cast<const float4*>(h);
        float4 w = __ldcs(Wr + tid), v = hv[tid];
        float acc = w.x * v.x + w.y * v.y + w.z * v.z + w.w * v.w;
        acc = warp_sum(acc);
        if (lane == 0) s_r[wid] = acc;
        __syncthreads();
        if (tid == 0) {
            float s = 0.f;
            #pragma unroll
            for (int w2 = 0; w2 < 8; w2++) s += s_r[w2];
            g_hg[r] = s + bhh[r];
        }
    }
}

// K2: softmax over scores (per-block recompute), attn_applied, embed copy, attn_w out
//     4 blocks x 256 thr; block bk covers elements bk*256..bk*256+255
__global__ void __launch_bounds__(256)
k2_apply(const int* __restrict__ x, const float* __restrict__ enc,
         const float* __restrict__ emb, float* __restrict__ out) {
    __shared__ float s_w[MAXLEN];
    const int tid = threadIdx.x;
    if (tid == 0) {
        float mx = -1e30f;
        #pragma unroll
        for (int m = 0; m < MAXLEN; m++) mx = fmaxf(mx, g_scores[m]);
        float s = 0.f;
        #pragma unroll
        for (int m = 0; m < MAXLEN; m++) { float e = expf(g_scores[m] - mx); s_w[m] = e; s += e; }
        float inv = 1.f / s;
        #pragma unroll
        for (int m = 0; m < MAXLEN; m++) s_w[m] *= inv;
    }
    __syncthreads();

    const int k = blockIdx.x * 256 + tid;                  // 0..1023
    if (blockIdx.x == 0 && tid < MAXLEN) out[V + H + tid] = s_w[tid];

    const long row = (long)x[0];
    g_u[k] = emb[row * H + k];
    float acc = 0.f;
    #pragma unroll
    for (int m = 0; m < MAXLEN; m++) acc += s_w[m] * enc[m * H + k];
    g_u[H + k] = acc;
}

// K3: comb = relu(W_comb @ u + b_comb); block per row (1024 blocks x 256 thr)
__global__ void __launch_bounds__(256)
k3_comb(const float* __restrict__ Wc, const float* __restrict__ bc) {
    __shared__ float s_r[8];
    const int tid = threadIdx.x, wid = tid >> 5, lane = tid & 31;
    const int r = blockIdx.x;
    const float4* Wr = reinterpret_cast<const float4*>(Wc + (long)r * (2 * H));
    const float4* u4 = reinterpret_cast<const float4*>(g_u);
    float4 w0 = __ldcs(Wr + tid),       v0 = u4[tid];
    float4 w1 = __ldcs(Wr + tid + 256), v1 = u4[tid + 256];
    float acc = w0.x * v0.x + w0.y * v0.y + w0.z * v0.z + w0.w * v0.w
              + w1.x * v1.x + w1.y * v1.y + w1.z * v1.z + w1.w * v1.w;
    acc = warp_sum(acc);
    if (lane == 0) s_r[wid] = acc;
    __syncthreads();
    if (tid == 0) {
        float s = 0.f;
        #pragma unroll
        for (int w = 0; w < 8; w++) s += s_r[w];
        g_comb[r] = fmaxf(s + bc[r], 0.f);
    }
}

// K4: GRU gates + update; block per j (1024 blocks x 256 thr); 3 dots per block
__global__ void __launch_bounds__(256)
k4_gru(const float* __restrict__ Wih, const float* __restrict__ bih,
       const float* __restrict__ h, float* __restrict__ out) {
    __shared__ float s0[8], s1[8], s2[8];
    const int tid = threadIdx.x, wid = tid >> 5, lane = tid & 31;
    const int j = blockIdx.x;
    const float4* W0 = reinterpret_cast<const float4*>(Wih + (long)j * H);
    const float4* W1 = reinterpret_cast<const float4*>(Wih + (long)(H + j) * H);
    const float4* W2 = reinterpret_cast<const float4*>(Wih + (long)(2 * H + j) * H);
    const float4* c4 = reinterpret_cast<const float4*>(g_comb);
    float4 v = c4[tid];
    float4 w0 = __ldcs(W0 + tid), w1 = __ldcs(W1 + tid), w2 = __ldcs(W2 + tid);
    float a0 = w0.x * v.x + w0.y * v.y + w0.z * v.z + w0.w * v.w;
    float a1 = w1.x * v.x + w1.y * v.y + w1.z * v.z + w1.w * v.w;
    float a2 = w2.x * v.x + w2.y * v.y + w2.z * v.z + w2.w * v.w;
    a0 = warp_sum(a0); a1 = warp_sum(a1); a2 = warp_sum(a2);
    if (lane == 0) { s0[wid] = a0; s1[wid] = a1; s2[wid] = a2; }
    __syncthreads();
    if (tid == 0) {
        float x0 = 0.f, x1 = 0.f, x2 = 0.f;
        #pragma unroll
        for (int w = 0; w < 8; w++) { x0 += s0[w]; x1 += s1[w]; x2 += s2[w]; }
        float xr = x0 + bih[j];
        float xz = x1 + bih[H + j];
        float xn = x2 + bih[2 * H + j];
        float rr = 1.f / (1.f + expf(-(xr + g_hg[j])));
        float zz = 1.f / (1.f + expf(-(xz + g_hg[H + j])));
        float nn = tanhf(xn + rr * g_hg[2 * H + j]);
        float hv = (1.f - zz) * nn + zz * h[j];
        g_hnew[j] = hv;
        out[V + j] = hv;
    }
}

// K5: logits = W_out @ hnew + b_out; 6250 blocks x 256 thr; warp per row;
//     per-block (max, sum exp) partials  -- unchanged from R16 (proven 76% DRAM)
__global__ void __launch_bounds__(256)
k5_logits(const float* __restrict__ Wo, const float* __restrict__ bo) {
    __shared__ float4 s_h[H / 4];
    __shared__ float s_l[8];
    const int tid = threadIdx.x, wid = tid >> 5, lane = tid & 31;
    s_h[tid] = reinterpret_cast<const float4*>(g_hnew)[tid];
    __syncthreads();

    const int r = blockIdx.x * 8 + wid;                    // < V exactly
    float bv = 0.f;
    if (lane == 0) bv = __ldcs(bo + r);
    const float4* Wr = reinterpret_cast<const float4*>(Wo + (long)r * H);
    float acc = 0.f;
    #pragma unroll
    for (int c = lane; c < H / 4; c += 32) {
        float4 w = __ldcs(Wr + c), v = s_h[c];
        acc += w.x * v.x + w.y * v.y + w.z * v.z + w.w * v.w;
    }
    acc = warp_sum(acc);
    if (lane == 0) {
        float lg = acc + bv;
        g_logits[r] = lg;
        s_l[wid] = lg;
    }
    __syncthreads();
    if (tid == 0) {
        float m = s_l[0];
        #pragma unroll
        for (int w = 1; w < 8; w++) m = fmaxf(m, s_l[w]);
        float s = 0.f;
        #pragma unroll
        for (int w = 0; w < 8; w++) s += expf(s_l[w] - m);
        g_bm[blockIdx.x] = m;
        g_bs[blockIdx.x] = s;
    }
}

// K6: reduce 6250 (m,s) pairs -> M + log(S); 1 block x 1024 thr
__global__ void __launch_bounds__(1024)
k6_red() {
    __shared__ float sm[32], ss[32];
    const int tid = threadIdx.x, lane = tid & 31, w = tid >> 5;
    float M = -1e30f, S = 0.f;
    for (int i = tid; i < NBLK5; i += 1024) {
        float m2 = g_bm[i], s2 = g_bs[i];
        float nm = fmaxf(M, m2);
        S = S * expf(M - nm) + s2 * expf(m2 - nm);
        M = nm;
    }
    #pragma unroll
    for (int o = 16; o > 0; o >>= 1) {
        float m2 = __shfl_down_sync(0xffffffffu, M, o);
        float s2 = __shfl_down_sync(0xffffffffu, S, o);
        float nm = fmaxf(M, m2);
        S = S * expf(M - nm) + s2 * expf(m2 - nm);
        M = nm;
    }
    if (lane == 0) { sm[w] = M; ss[w] = S; }
    __syncthreads();
    if (tid < 32) {
        float m1 = sm[tid], s1 = ss[tid];
        #pragma unroll
        for (int o = 16; o > 0; o >>= 1) {
            float m2 = __shfl_down_sync(0xffffffffu, m1, o);
            float s2 = __shfl_down_sync(0xffffffffu, s1, o);
            float nm = fmaxf(m1, m2);
            s1 = s1 * expf(m1 - nm) + s2 * expf(m2 - nm);
            m1 = nm;
        }
        if (tid == 0) g_red[0] = m1 + logf(s1);
    }
}

// K7: logp = logits - (M + log S); vectorized
__global__ void __launch_bounds__(256)
k7_out(float* __restrict__ out) {
    const int i = blockIdx.x * 256 + threadIdx.x;          // float4 index
    const float off = g_red[0];
    if (i < V / 4) {
        float4 l = reinterpret_cast<const float4*>(g_logits)[i];
        float4 o;
        o.x = l.x - off; o.y = l.y - off; o.z = l.z - off; o.w = l.w - off;
        reinterpret_cast<float4*>(out)[i] = o;
    }
}

extern "C" void kernel_launch(void* const* d_in, const int* in_sizes, int n_in,
                              void* d_out, int out_size) {
    const int*   x   = (const int*)  d_in[0];
    const float* h   = (const float*)d_in[1];   // h_state (1,1,H)
    const float* enc = (const float*)d_in[3];   // encoder_outputs
    const float* emb = (const float*)d_in[4];
    const float* Wa  = (const float*)d_in[5];
    const float* ba  = (const float*)d_in[6];
    const float* Wc  = (const float*)d_in[7];
    const float* bc  = (const float*)d_in[8];
    const float* Wih = (const float*)d_in[9];
    const float* bih = (const float*)d_in[10];
    const float* Whh = (const float*)d_in[11];
    const float* bhh = (const float*)d_in[12];
    const float* Wo  = (const float*)d_in[13];
    const float* bo  = (const float*)d_in[14];
    float* out = (float*)d_out;

    k1_scores_hg<<<MAXLEN + 3 * H, 256>>>(x, h, emb, Wa, ba, Whh, bhh);
    k2_apply<<<4, 256>>>(x, enc, emb, out);
    k3_comb<<<H, 256>>>(Wc, bc);
    k4_gru<<<H, 256>>>(Wih, bih, h, out);
    k5_logits<<<NBLK5, 256>>>(Wo, bo);
    k6_red<<<1, 1024>>>();
    k7_out<<<(V / 4 + 255) / 256, 256>>>(out);
}